// round 1
// baseline (speedup 1.0000x reference)
#include <cuda_runtime.h>
#include <cstdint>

// ---------------- problem constants ----------------
#define NB       16
#define NFEAT    1572864      // 8192*192 = x_f elements (524288 rows x 3)
#define N_P      65536
#define EH       2097152      // edges used (even columns)
#define E_TOTAL  4194304
#define XP_N     6553600      // 65536*100 == 16*100*4096
#define L0       4096
#define L1V      4095
#define L2V      4094
#define KDIM     409400       // (SEQ-2)*100
#define O1       500
#define NCLS     107

// ---------------- scratch (device globals; no allocation) ----------------
__device__ float g_xf[NFEAT];
__device__ float g_agg[N_P * 4];          // sum3 + count
__device__ float g_xp[XP_N];
__device__ float g_out1[NB * 100 * L1V];
__device__ float g_out2[NB * 100 * L2V];
__device__ float g_y1[O1 * NB];           // dense1 accumulator, [o][b]

// ---------------- zero init ----------------
__global__ void zero_kernel() {
    int i = blockIdx.x * 256 + threadIdx.x;
    if (i < N_P * 4) g_agg[i] = 0.0f;
    if (i < O1 * NB) g_y1[i] = 0.0f;
}

// ---------------- x_f = x_src @ W_fd.T + b_fd  (flat 8192x192) ----------------
__global__ void feat_kernel(const float* __restrict__ xsrc,
                            const float* __restrict__ Wfd,
                            const float* __restrict__ bfd) {
    int gid = blockIdx.x * 256 + threadIdx.x;   // < 1572864 exactly
    int i = gid / 192;
    int j = gid - i * 192;
    const float* xr = xsrc + i * 64;
    const float* wr = Wfd + j * 64;
    float s = bfd[j];
#pragma unroll 8
    for (int k = 0; k < 64; k++) s = fmaf(__ldg(xr + k), __ldg(wr + k), s);
    g_xf[gid] = s;
}

// ---------------- edge aggregation (segment sum + count) ----------------
__global__ void edge_kernel(const int* __restrict__ ei) {
    int e = blockIdx.x * 256 + threadIdx.x;     // < 2097152 exactly
    int src = ei[2 * e];                        // row 0, even cols -> [0, N_F)
    int dst = ei[E_TOTAL + 2 * e];              // row 1, even cols -> [0, N_P)
    const float* p = g_xf + 3 * src;
    float v0 = p[0], v1 = p[1], v2 = p[2];
    float* a = g_agg + 4 * dst;
    atomicAdd(a + 0, v0);
    atomicAdd(a + 1, v1);
    atomicAdd(a + 2, v2);
    atomicAdd(a + 3, 1.0f);
}

// ---------------- x_p = relu(mean @ W_l1.T + b_l1 + x_p0 @ W_r1.T) ----------------
__global__ void node_kernel(const float* __restrict__ xdst,
                            const float* __restrict__ Wl1,
                            const float* __restrict__ bl1,
                            const float* __restrict__ Wr1) {
    int gid = blockIdx.x * 256 + threadIdx.x;   // < 6553600 exactly
    int n = gid / 100;
    int c = gid - n * 100;
    const float* a = g_agg + 4 * n;
    float inv = 1.0f / fmaxf(a[3], 1.0f);
    float m0 = a[0] * inv, m1 = a[1] * inv, m2 = a[2] * inv;
    float v = bl1[c];
    v = fmaf(m0, __ldg(Wl1 + c * 3 + 0), v);
    v = fmaf(m1, __ldg(Wl1 + c * 3 + 1), v);
    v = fmaf(m2, __ldg(Wl1 + c * 3 + 2), v);
    const float* xd = xdst + 3 * n;
    v = fmaf(xd[0], __ldg(Wr1 + c * 3 + 0), v);
    v = fmaf(xd[1], __ldg(Wr1 + c * 3 + 1), v);
    v = fmaf(xd[2], __ldg(Wr1 + c * 3 + 2), v);
    g_xp[gid] = fmaxf(v, 0.0f);
}

// ---------------- conv (k=2, 100->100 channels) + relu ----------------
// grid (16, 64), block 200 threads. h-tile = 64 per block.
// smem: ws[100][2][100] (layout [i][k][o]) = 80000B, xs[100][65] = 26000B
#define CONV_SMEM ((20000 + 6500) * 4)
__global__ __launch_bounds__(200)
void conv_kernel(const float* __restrict__ in, const float* __restrict__ W,
                 float* __restrict__ out, int Lin, int Lout) {
    extern __shared__ float sm[];
    float* ws = sm;            // [(i*2+k)*100 + o]
    float* xs = sm + 20000;    // [i*65 + j]
    int b  = blockIdx.x;
    int h0 = blockIdx.y << 6;
    int t  = threadIdx.x;

    for (int idx = t; idx < 20000; idx += 200) {
        int o = idx / 200;
        int r = idx - o * 200;            // i*2+k
        ws[r * 100 + o] = W[idx];
    }
    int nj = Lin - h0; if (nj > 65) nj = 65;
    const float* inb = in + (size_t)b * 100 * Lin + h0;
    for (int idx = t; idx < 6500; idx += 200) {
        int i = idx / 65;
        int j = idx - i * 65;
        xs[idx] = (j < nj) ? inb[(size_t)i * Lin + j] : 0.0f;
    }
    __syncthreads();

    int og = t >> 3, ht = t & 7;
    int o0 = og << 2, hh = ht << 3;
    float acc[4][8];
#pragma unroll
    for (int oo = 0; oo < 4; oo++)
#pragma unroll
        for (int j = 0; j < 8; j++) acc[oo][j] = 0.0f;

    for (int i = 0; i < 100; i++) {
        float x[9];
#pragma unroll
        for (int j = 0; j < 9; j++) x[j] = xs[i * 65 + hh + j];
#pragma unroll
        for (int oo = 0; oo < 4; oo++) {
            float w0 = ws[(i * 2 + 0) * 100 + o0 + oo];
            float w1 = ws[(i * 2 + 1) * 100 + o0 + oo];
#pragma unroll
            for (int j = 0; j < 8; j++)
                acc[oo][j] = fmaf(w0, x[j], fmaf(w1, x[j + 1], acc[oo][j]));
        }
    }

    float* outb = out + (size_t)b * 100 * Lout;
#pragma unroll
    for (int oo = 0; oo < 4; oo++)
#pragma unroll
        for (int j = 0; j < 8; j++) {
            int h = h0 + hh + j;
            if (h < Lout)
                outb[(size_t)(o0 + oo) * Lout + h] = fmaxf(acc[oo][j], 0.0f);
        }
}

// ---------------- dense1: y1[o][b] += sum_k x2[b][k] * W[o][k] ----------------
// grid 400 (K-chunks of 1024), block 128. Each thread owns 4 full o-rows x 16 b.
#define D1_SMEM (16 * 1024 * 4)
__global__ __launch_bounds__(128)
void dense1_kernel(const float* __restrict__ x2, const float* __restrict__ W) {
    extern __shared__ float xs[];   // [16][1024]
    int k0 = blockIdx.x << 10;
    int KN = KDIM - k0; if (KN > 1024) KN = 1024;   // 1024 or 824; both %4==0

    for (int idx = threadIdx.x; idx < 4096; idx += 128) {
        int b  = idx >> 8;
        int kk = (idx & 255) << 2;
        float4 v = make_float4(0.f, 0.f, 0.f, 0.f);
        if (kk < KN)
            v = *reinterpret_cast<const float4*>(x2 + (size_t)b * KDIM + k0 + kk);
        *reinterpret_cast<float4*>(&xs[(b << 10) + kk]) = v;
    }
    __syncthreads();

    int o0 = threadIdx.x << 2;
    if (o0 >= O1) return;

    float acc[4][16];
#pragma unroll
    for (int i = 0; i < 4; i++)
#pragma unroll
        for (int b = 0; b < 16; b++) acc[i][b] = 0.0f;

    const float* w0 = W + (size_t)o0 * KDIM + k0;
    for (int k = 0; k < KN; k += 4) {
        float4 w[4];
#pragma unroll
        for (int i = 0; i < 4; i++)
            w[i] = *reinterpret_cast<const float4*>(w0 + (size_t)i * KDIM + k);
#pragma unroll
        for (int b = 0; b < 16; b++) {
            float4 xv = *reinterpret_cast<const float4*>(&xs[(b << 10) + k]);
#pragma unroll
            for (int i = 0; i < 4; i++) {
                acc[i][b] = fmaf(w[i].x, xv.x, acc[i][b]);
                acc[i][b] = fmaf(w[i].y, xv.y, acc[i][b]);
                acc[i][b] = fmaf(w[i].z, xv.z, acc[i][b]);
                acc[i][b] = fmaf(w[i].w, xv.w, acc[i][b]);
            }
        }
    }
#pragma unroll
    for (int i = 0; i < 4; i++)
#pragma unroll
        for (int b = 0; b < 16; b++)
            atomicAdd(&g_y1[(o0 + i) * 16 + b], acc[i][b]);
}

// ---------------- dense2 + softmax ----------------
__global__ void dense2_kernel(const float* __restrict__ Wd2, float* __restrict__ out) {
    __shared__ float ys[O1];
    __shared__ float red[128];
    int b = blockIdx.x, t = threadIdx.x;
    for (int o = t; o < O1; o += 128) ys[o] = fmaxf(g_y1[o * 16 + b], 0.0f);
    __syncthreads();

    float logit = -1e30f;
    if (t < NCLS) {
        float s = 0.0f;
        const float* wr = Wd2 + t * O1;
        for (int o = 0; o < O1; o++) s = fmaf(ys[o], __ldg(wr + o), s);
        logit = s;
    }
    red[t] = logit;
    __syncthreads();
    for (int s = 64; s > 0; s >>= 1) {
        if (t < s) red[t] = fmaxf(red[t], red[t + s]);
        __syncthreads();
    }
    float mx = red[0];
    __syncthreads();
    float e = (t < NCLS) ? expf(logit - mx) : 0.0f;
    red[t] = e;
    __syncthreads();
    for (int s = 64; s > 0; s >>= 1) {
        if (t < s) red[t] += red[t + s];
        __syncthreads();
    }
    float sum = red[0];
    if (t < NCLS) out[b * NCLS + t] = e / sum;
}

// ---------------- launch ----------------
extern "C" void kernel_launch(void* const* d_in, const int* in_sizes, int n_in,
                              void* d_out, int out_size) {
    const float* x_src = (const float*)d_in[0];
    const float* x_dst = (const float*)d_in[1];
    const int*   ei    = (const int*)  d_in[2];
    const float* Wfd   = (const float*)d_in[3];
    const float* bfd   = (const float*)d_in[4];
    const float* Wl1   = (const float*)d_in[5];
    const float* bl1   = (const float*)d_in[6];
    const float* Wr1   = (const float*)d_in[7];
    // d_in[8..10] = W_l2, b_l2, W_r2 : dead code in the reference (x_f branch unused)
    const float* Wc1   = (const float*)d_in[11];
    const float* Wc2   = (const float*)d_in[12];
    const float* Wd1   = (const float*)d_in[13];
    const float* Wd2   = (const float*)d_in[14];
    float* out = (float*)d_out;

    float *p_xp, *p_o1, *p_o2;
    cudaGetSymbolAddress((void**)&p_xp, g_xp);
    cudaGetSymbolAddress((void**)&p_o1, g_out1);
    cudaGetSymbolAddress((void**)&p_o2, g_out2);

    cudaFuncSetAttribute(conv_kernel,  cudaFuncAttributeMaxDynamicSharedMemorySize, CONV_SMEM);
    cudaFuncSetAttribute(dense1_kernel, cudaFuncAttributeMaxDynamicSharedMemorySize, D1_SMEM);

    zero_kernel<<<(N_P * 4 + 255) / 256, 256>>>();
    feat_kernel<<<NFEAT / 256, 256>>>(x_src, Wfd, bfd);
    edge_kernel<<<EH / 256, 256>>>(ei);
    node_kernel<<<XP_N / 256, 256>>>(x_dst, Wl1, bl1, Wr1);
    conv_kernel<<<dim3(16, 64), 200, CONV_SMEM>>>(p_xp, Wc1, p_o1, L0, L1V);
    conv_kernel<<<dim3(16, 64), 200, CONV_SMEM>>>(p_o1, Wc2, p_o2, L1V, L2V);
    dense1_kernel<<<400, 128, D1_SMEM>>>(p_o2, Wd1);
    dense2_kernel<<<NB, 128>>>(Wd2, out);
}

// round 2
// speedup vs baseline: 1.4960x; 1.4960x over previous
#include <cuda_runtime.h>
#include <cstdint>

// ---------------- problem constants ----------------
#define NB       16
#define NFEAT    1572864      // 8192*192
#define N_P      65536
#define EH       2097152      // edges used (even columns)
#define E_TOTAL  4194304
#define XP_N     6553600
#define L0       4096
#define L1V      4095
#define L2V      4094
#define KDIM     409400       // (SEQ-2)*100
#define O1       500
#define NCLS     107

// ---------------- packed fp32x2 helpers ----------------
__device__ __forceinline__ double pk2(float lo, float hi) {
    double d; asm("mov.b64 %0, {%1, %2};" : "=d"(d) : "f"(lo), "f"(hi)); return d;
}
__device__ __forceinline__ void upk2(double d, float& lo, float& hi) {
    asm("mov.b64 {%0, %1}, %2;" : "=f"(lo), "=f"(hi) : "d"(d));
}
__device__ __forceinline__ double ffma2(double a, double b, double c) {
    double d; asm("fma.rn.f32x2 %0, %1, %2, %3;" : "=d"(d) : "d"(a), "d"(b), "d"(c)); return d;
}

// ---------------- scratch ----------------
__device__ float g_xf[NFEAT];
__device__ float g_agg[N_P * 4];
__device__ float g_xp[XP_N];
__device__ float g_out1[NB * 100 * L1V];
__device__ float g_out2[NB * 100 * L2V];
__device__ float g_y1[O1 * NB];

// ---------------- zero init ----------------
__global__ void zero_kernel() {
    int i = blockIdx.x * 256 + threadIdx.x;
    if (i < N_P * 4) g_agg[i] = 0.0f;
    if (i < O1 * NB) g_y1[i] = 0.0f;
}

// ---------------- feat: x_f = x_src @ W_fd.T + b_fd (8192x64 @ 64x192) ----------------
// grid 128 (64 i-rows each), block 256 (16 tx x 16 ty). smem tiled, LDS broadcast.
#define FEAT_SMEM ((64 * 65 + 192 * 65) * 4)
__global__ __launch_bounds__(256)
void feat_kernel(const float* __restrict__ xsrc,
                 const float* __restrict__ Wfd,
                 const float* __restrict__ bfd) {
    extern __shared__ float sm[];
    float* xs = sm;             // [64][65]
    float* ws = sm + 64 * 65;   // [192][65]
    int t = threadIdx.x;
    int i0 = blockIdx.x << 6;

    for (int idx = t; idx < 4096; idx += 256) {
        int i = idx >> 6, k = idx & 63;
        xs[i * 65 + k] = xsrc[(i0 + i) * 64 + k];
    }
    for (int idx = t; idx < 12288; idx += 256) {
        int j = idx >> 6, k = idx & 63;
        ws[j * 65 + k] = Wfd[idx];
    }
    __syncthreads();

    int tx = t & 15, ty = t >> 4;      // tx: j-groups of 12, ty: i-groups of 4
    float acc[4][12];
#pragma unroll
    for (int ii = 0; ii < 4; ii++)
#pragma unroll
        for (int jj = 0; jj < 12; jj++) acc[ii][jj] = 0.0f;

    for (int k = 0; k < 64; k++) {
        float xv[4], wv[12];
#pragma unroll
        for (int ii = 0; ii < 4; ii++) xv[ii] = xs[(ty * 4 + ii) * 65 + k];
#pragma unroll
        for (int jj = 0; jj < 12; jj++) wv[jj] = ws[(tx * 12 + jj) * 65 + k];
#pragma unroll
        for (int ii = 0; ii < 4; ii++)
#pragma unroll
            for (int jj = 0; jj < 12; jj++)
                acc[ii][jj] = fmaf(xv[ii], wv[jj], acc[ii][jj]);
    }

#pragma unroll
    for (int ii = 0; ii < 4; ii++) {
        int i = i0 + ty * 4 + ii;
        int j0 = tx * 12;
#pragma unroll
        for (int q = 0; q < 3; q++) {
            float4 v;
            v.x = acc[ii][q * 4 + 0] + __ldg(bfd + j0 + q * 4 + 0);
            v.y = acc[ii][q * 4 + 1] + __ldg(bfd + j0 + q * 4 + 1);
            v.z = acc[ii][q * 4 + 2] + __ldg(bfd + j0 + q * 4 + 2);
            v.w = acc[ii][q * 4 + 3] + __ldg(bfd + j0 + q * 4 + 3);
            *reinterpret_cast<float4*>(&g_xf[i * 192 + j0 + q * 4]) = v;
        }
    }
}

// ---------------- edge aggregation ----------------
__global__ void edge_kernel(const int* __restrict__ ei) {
    int e = blockIdx.x * 256 + threadIdx.x;
    int src = ei[2 * e];
    int dst = ei[E_TOTAL + 2 * e];
    const float* p = g_xf + 3 * src;
    float v0 = p[0], v1 = p[1], v2 = p[2];
    float* a = g_agg + 4 * dst;
    atomicAdd(a + 0, v0);
    atomicAdd(a + 1, v1);
    atomicAdd(a + 2, v2);
    atomicAdd(a + 3, 1.0f);
}

// ---------------- node update: 4 channels per thread, float4 I/O ----------------
__global__ void node_kernel(const float* __restrict__ xdst,
                            const float* __restrict__ Wl1,
                            const float* __restrict__ bl1,
                            const float* __restrict__ Wr1) {
    int gid = blockIdx.x * 256 + threadIdx.x;   // < 1638400 exactly
    int n = gid / 25;
    int c0 = (gid - n * 25) * 4;
    float4 a = *reinterpret_cast<const float4*>(&g_agg[n * 4]);
    float inv = __fdividef(1.0f, fmaxf(a.w, 1.0f));
    float m0 = a.x * inv, m1 = a.y * inv, m2 = a.z * inv;
    const float* xd = xdst + 3 * n;
    float d0 = xd[0], d1 = xd[1], d2 = xd[2];
    float r[4];
#pragma unroll
    for (int cc = 0; cc < 4; cc++) {
        int c = c0 + cc;
        float v = __ldg(bl1 + c);
        v = fmaf(m0, __ldg(Wl1 + c * 3 + 0), v);
        v = fmaf(m1, __ldg(Wl1 + c * 3 + 1), v);
        v = fmaf(m2, __ldg(Wl1 + c * 3 + 2), v);
        v = fmaf(d0, __ldg(Wr1 + c * 3 + 0), v);
        v = fmaf(d1, __ldg(Wr1 + c * 3 + 1), v);
        v = fmaf(d2, __ldg(Wr1 + c * 3 + 2), v);
        r[cc] = fmaxf(v, 0.0f);
    }
    *reinterpret_cast<float4*>(&g_xp[n * 100 + c0]) =
        make_float4(r[0], r[1], r[2], r[3]);
}

// ---------------- conv (k=2, 100->100) with packed f32x2 over k-pairs ----------------
// ws layout [o][i*2+k] stride 202 (w-pairs = native LDS.64, conflict-free across og)
// xs layout [i][j] stride 68 (float4-aligned)
#define CONV_SMEM ((100 * 202 + 100 * 68) * 4)
__global__ __launch_bounds__(200)
void conv_kernel(const float* __restrict__ in, const float* __restrict__ W,
                 float* __restrict__ out, int Lin, int Lout) {
    extern __shared__ float sm[];
    float* ws = sm;               // [o][202]
    float* xs = sm + 100 * 202;   // [i][68]
    int b  = blockIdx.x;
    int h0 = blockIdx.y << 6;
    int t  = threadIdx.x;

    for (int idx = t; idx < 20000; idx += 200) {
        int o = idx / 200;
        ws[o * 202 + (idx - o * 200)] = W[idx];
    }
    int nj = Lin - h0; if (nj > 65) nj = 65;
    const float* inb = in + b * 100 * Lin + h0;
    for (int idx = t; idx < 6800; idx += 200) {
        int i = idx / 68;
        int j = idx - i * 68;
        xs[idx] = (j < nj) ? inb[i * Lin + j] : 0.0f;
    }
    __syncthreads();

    int og = t >> 3, ht = t & 7;
    int o0 = og << 2, hh = ht << 3;
    double acc2[4][8];
#pragma unroll
    for (int oo = 0; oo < 4; oo++)
#pragma unroll
        for (int j = 0; j < 8; j++) acc2[oo][j] = 0.0;

    for (int i = 0; i < 100; i++) {
        const float* xr = xs + i * 68 + hh;
        float4 xA = *reinterpret_cast<const float4*>(xr);
        float4 xB = *reinterpret_cast<const float4*>(xr + 4);
        float x8 = xr[8];
        double xp[8];
        xp[0] = pk2(xA.x, xA.y); xp[1] = pk2(xA.y, xA.z);
        xp[2] = pk2(xA.z, xA.w); xp[3] = pk2(xA.w, xB.x);
        xp[4] = pk2(xB.x, xB.y); xp[5] = pk2(xB.y, xB.z);
        xp[6] = pk2(xB.z, xB.w); xp[7] = pk2(xB.w, x8);
#pragma unroll
        for (int oo = 0; oo < 4; oo++) {
            double wp = *reinterpret_cast<const double*>(&ws[(o0 + oo) * 202 + i * 2]);
#pragma unroll
            for (int j = 0; j < 8; j++)
                acc2[oo][j] = ffma2(wp, xp[j], acc2[oo][j]);
        }
    }

    float* outb = out + b * 100 * Lout;
#pragma unroll
    for (int oo = 0; oo < 4; oo++)
#pragma unroll
        for (int j = 0; j < 8; j++) {
            int h = h0 + hh + j;
            if (h < Lout) {
                float lo, hi; upk2(acc2[oo][j], lo, hi);
                outb[(o0 + oo) * Lout + h] = fmaxf(lo + hi, 0.0f);
            }
        }
}

// ---------------- dense1: lanes split k (coalesced W), f32x2 packed ----------------
// grid (400 k-chunks, 16 o-tiles, 2 b-halves). block 256 = 8 warps, warp = 4 o x 8 b.
#define D1_SMEM (8 * 1024 * 4)
__global__ __launch_bounds__(256, 2)
void dense1_kernel(const float* __restrict__ x2, const float* __restrict__ W) {
    extern __shared__ float xs[];   // [8][1024]
    int t = threadIdx.x;
    int k0 = blockIdx.x << 10;
    int KN = KDIM - k0; if (KN > 1024) KN = 1024;   // 1024 or 824, both %4==0
    int b0 = blockIdx.z << 3;

    for (int idx = t; idx < 2048; idx += 256) {
        int b = idx >> 8;
        int kk = (idx & 255) << 2;
        float4 v = make_float4(0.f, 0.f, 0.f, 0.f);
        if (kk < KN)
            v = *reinterpret_cast<const float4*>(x2 + (size_t)(b0 + b) * KDIM + k0 + kk);
        *reinterpret_cast<float4*>(&xs[(b << 10) + kk]) = v;
    }
    __syncthreads();

    int wid = t >> 5, lane = t & 31;
    int o0 = (blockIdx.y << 5) + (wid << 2);
    if (o0 >= O1) return;

    double acc2[4][8];
#pragma unroll
    for (int o = 0; o < 4; o++)
#pragma unroll
        for (int b = 0; b < 8; b++) acc2[o][b] = 0.0;

    const float* wrow = W + (size_t)o0 * KDIM + k0;
    for (int kk = lane * 4; kk < KN; kk += 128) {
        double2 w[4];
#pragma unroll
        for (int o = 0; o < 4; o++)
            w[o] = *reinterpret_cast<const double2*>(wrow + (size_t)o * KDIM + kk);
#pragma unroll
        for (int b = 0; b < 8; b++) {
            double2 xv = *reinterpret_cast<const double2*>(&xs[(b << 10) + kk]);
#pragma unroll
            for (int o = 0; o < 4; o++) {
                acc2[o][b] = ffma2(w[o].x, xv.x, acc2[o][b]);
                acc2[o][b] = ffma2(w[o].y, xv.y, acc2[o][b]);
            }
        }
    }

    // collapse halves, warp-reduce across k-lanes, one atomic per (o,b)
    float s[32];
#pragma unroll
    for (int o = 0; o < 4; o++)
#pragma unroll
        for (int b = 0; b < 8; b++) {
            float lo, hi; upk2(acc2[o][b], lo, hi);
            s[o * 8 + b] = lo + hi;
        }
#pragma unroll
    for (int a = 0; a < 32; a++) {
        float v = s[a];
        v += __shfl_xor_sync(0xffffffffu, v, 16);
        v += __shfl_xor_sync(0xffffffffu, v, 8);
        v += __shfl_xor_sync(0xffffffffu, v, 4);
        v += __shfl_xor_sync(0xffffffffu, v, 2);
        v += __shfl_xor_sync(0xffffffffu, v, 1);
        if (lane == a)
            atomicAdd(&g_y1[(o0 + (a >> 3)) * 16 + b0 + (a & 7)], v);
    }
}

// ---------------- dense2 + softmax ----------------
__global__ void dense2_kernel(const float* __restrict__ Wd2, float* __restrict__ out) {
    __shared__ float ys[O1];
    __shared__ float red[128];
    int b = blockIdx.x, t = threadIdx.x;
    for (int o = t; o < O1; o += 128) ys[o] = fmaxf(g_y1[o * 16 + b], 0.0f);
    __syncthreads();

    float logit = -1e30f;
    if (t < NCLS) {
        float s = 0.0f;
        const float* wr = Wd2 + t * O1;
        for (int o = 0; o < O1; o++) s = fmaf(ys[o], __ldg(wr + o), s);
        logit = s;
    }
    red[t] = logit;
    __syncthreads();
    for (int s = 64; s > 0; s >>= 1) {
        if (t < s) red[t] = fmaxf(red[t], red[t + s]);
        __syncthreads();
    }
    float mx = red[0];
    __syncthreads();
    float e = (t < NCLS) ? expf(logit - mx) : 0.0f;
    red[t] = e;
    __syncthreads();
    for (int s = 64; s > 0; s >>= 1) {
        if (t < s) red[t] += red[t + s];
        __syncthreads();
    }
    float sum = red[0];
    if (t < NCLS) out[b * NCLS + t] = e / sum;
}

// ---------------- launch ----------------
extern "C" void kernel_launch(void* const* d_in, const int* in_sizes, int n_in,
                              void* d_out, int out_size) {
    const float* x_src = (const float*)d_in[0];
    const float* x_dst = (const float*)d_in[1];
    const int*   ei    = (const int*)  d_in[2];
    const float* Wfd   = (const float*)d_in[3];
    const float* bfd   = (const float*)d_in[4];
    const float* Wl1   = (const float*)d_in[5];
    const float* bl1   = (const float*)d_in[6];
    const float* Wr1   = (const float*)d_in[7];
    // d_in[8..10] dead (x_f second layer unused by reference)
    const float* Wc1   = (const float*)d_in[11];
    const float* Wc2   = (const float*)d_in[12];
    const float* Wd1   = (const float*)d_in[13];
    const float* Wd2   = (const float*)d_in[14];
    float* out = (float*)d_out;

    float *p_xp, *p_o1, *p_o2;
    cudaGetSymbolAddress((void**)&p_xp, g_xp);
    cudaGetSymbolAddress((void**)&p_o1, g_out1);
    cudaGetSymbolAddress((void**)&p_o2, g_out2);

    cudaFuncSetAttribute(feat_kernel, cudaFuncAttributeMaxDynamicSharedMemorySize, FEAT_SMEM);
    cudaFuncSetAttribute(conv_kernel, cudaFuncAttributeMaxDynamicSharedMemorySize, CONV_SMEM);

    zero_kernel<<<(N_P * 4 + 255) / 256, 256>>>();
    feat_kernel<<<128, 256, FEAT_SMEM>>>(x_src, Wfd, bfd);
    edge_kernel<<<EH / 256, 256>>>(ei);
    node_kernel<<<6400, 256>>>(x_dst, Wl1, bl1, Wr1);
    conv_kernel<<<dim3(16, 64), 200, CONV_SMEM>>>(p_xp, Wc1, p_o1, L0, L1V);
    conv_kernel<<<dim3(16, 64), 200, CONV_SMEM>>>(p_o1, Wc2, p_o2, L1V, L2V);
    dense1_kernel<<<dim3(400, 16, 2), 256, D1_SMEM>>>(p_o2, Wd1);
    dense2_kernel<<<NB, 128>>>(Wd2, out);
}

// round 3
// speedup vs baseline: 1.6479x; 1.1016x over previous
#include <cuda_runtime.h>
#include <cstdint>

// ---------------- problem constants ----------------
#define NB       16
#define N_F      524288       // x_f rows
#define N_P      65536
#define EH       2097152      // edges used (even columns)
#define E_TOTAL  4194304
#define XP_N     6553600
#define L0       4096
#define L1V      4095
#define L2V      4094
#define KDIM     409400       // (SEQ-2)*100
#define O1       500
#define NCLS     107

// ---------------- packed fp32x2 helpers ----------------
__device__ __forceinline__ double pk2(float lo, float hi) {
    double d; asm("mov.b64 %0, {%1, %2};" : "=d"(d) : "f"(lo), "f"(hi)); return d;
}
__device__ __forceinline__ void upk2(double d, float& lo, float& hi) {
    asm("mov.b64 {%0, %1}, %2;" : "=f"(lo), "=f"(hi) : "d"(d));
}
__device__ __forceinline__ double ffma2(double a, double b, double c) {
    double d; asm("fma.rn.f32x2 %0, %1, %2, %3;" : "=d"(d) : "d"(a), "d"(b), "d"(c)); return d;
}

// ---------------- scratch ----------------
__device__ float4 g_xf4[N_F];            // padded (v0,v1,v2,0)
__device__ float g_agg[N_P * 4];         // sum3 + count (one 16B slot per node)
__device__ float g_xp[XP_N];
__device__ float g_out1[NB * 100 * L1V];
__device__ float g_out2[NB * 100 * L2V];
__device__ float g_y1[O1 * NB];

// ---------------- zero init ----------------
__global__ void zero_kernel() {
    int i = blockIdx.x * 256 + threadIdx.x;
    if (i < N_P * 4) g_agg[i] = 0.0f;
    if (i < O1 * NB) g_y1[i] = 0.0f;
}

// ---------------- feat: x_f rows -> g_xf4 (8192x64 @ 64x192) ----------------
#define FEAT_SMEM ((64 * 65 + 192 * 65) * 4)
__global__ __launch_bounds__(256)
void feat_kernel(const float* __restrict__ xsrc,
                 const float* __restrict__ Wfd,
                 const float* __restrict__ bfd) {
    extern __shared__ float sm[];
    float* xs = sm;             // [64][65]
    float* ws = sm + 64 * 65;   // [192][65]
    int t = threadIdx.x;
    int i0 = blockIdx.x << 6;

    for (int idx = t; idx < 4096; idx += 256) {
        int i = idx >> 6, k = idx & 63;
        xs[i * 65 + k] = xsrc[(i0 + i) * 64 + k];
    }
    for (int idx = t; idx < 12288; idx += 256) {
        int j = idx >> 6, k = idx & 63;
        ws[j * 65 + k] = Wfd[idx];
    }
    __syncthreads();

    int tx = t & 15, ty = t >> 4;      // tx: j-groups of 12, ty: i-groups of 4
    float acc[4][12];
#pragma unroll
    for (int ii = 0; ii < 4; ii++)
#pragma unroll
        for (int jj = 0; jj < 12; jj++) acc[ii][jj] = 0.0f;

    for (int k = 0; k < 64; k++) {
        float xv[4], wv[12];
#pragma unroll
        for (int ii = 0; ii < 4; ii++) xv[ii] = xs[(ty * 4 + ii) * 65 + k];
#pragma unroll
        for (int jj = 0; jj < 12; jj++) wv[jj] = ws[(tx * 12 + jj) * 65 + k];
#pragma unroll
        for (int ii = 0; ii < 4; ii++)
#pragma unroll
            for (int jj = 0; jj < 12; jj++)
                acc[ii][jj] = fmaf(xv[ii], wv[jj], acc[ii][jj]);
    }

    int j0 = tx * 12;
#pragma unroll
    for (int ii = 0; ii < 4; ii++) {
        int i = i0 + ty * 4 + ii;                 // matrix row (0..8191)
#pragma unroll
        for (int rr = 0; rr < 4; rr++) {
            int r = i * 64 + tx * 4 + rr;         // xf row
            g_xf4[r] = make_float4(
                acc[ii][rr * 3 + 0] + __ldg(bfd + j0 + rr * 3 + 0),
                acc[ii][rr * 3 + 1] + __ldg(bfd + j0 + rr * 3 + 1),
                acc[ii][rr * 3 + 2] + __ldg(bfd + j0 + rr * 3 + 2),
                0.0f);
        }
    }
}

// ---------------- edge aggregation: 2 edges/thread, vector RED ----------------
__global__ void edge_kernel(const int* __restrict__ ei) {
    int e2 = blockIdx.x * 256 + threadIdx.x;      // < 1048576 exactly
    int4 s4 = *reinterpret_cast<const int4*>(ei + 4 * e2);            // srcs at .x, .z
    int4 d4 = *reinterpret_cast<const int4*>(ei + E_TOTAL + 4 * e2);  // dsts at .x, .z
    float4 v0 = g_xf4[s4.x];
    float4 v1 = g_xf4[s4.z];
    float* a0 = g_agg + 4 * d4.x;
    float* a1 = g_agg + 4 * d4.z;
    asm volatile("red.global.add.v4.f32 [%0], {%1, %2, %3, %4};"
                 :: "l"(a0), "f"(v0.x), "f"(v0.y), "f"(v0.z), "f"(1.0f) : "memory");
    asm volatile("red.global.add.v4.f32 [%0], {%1, %2, %3, %4};"
                 :: "l"(a1), "f"(v1.x), "f"(v1.y), "f"(v1.z), "f"(1.0f) : "memory");
}

// ---------------- node update: weights staged in smem ----------------
__global__ __launch_bounds__(256)
void node_kernel(const float* __restrict__ xdst,
                 const float* __restrict__ Wl1,
                 const float* __restrict__ bl1,
                 const float* __restrict__ Wr1) {
    __shared__ float swl[300], swr[300], sb[100];
    int t = threadIdx.x;
    for (int idx = t; idx < 300; idx += 256) { swl[idx] = Wl1[idx]; swr[idx] = Wr1[idx]; }
    if (t < 100) sb[t] = bl1[t];
    __syncthreads();

    int gid = blockIdx.x * 256 + t;               // < 1638400 exactly
    int n = gid / 25;
    int c0 = (gid - n * 25) * 4;
    float4 a = *reinterpret_cast<const float4*>(&g_agg[n * 4]);
    float inv = __fdividef(1.0f, fmaxf(a.w, 1.0f));
    float m0 = a.x * inv, m1 = a.y * inv, m2 = a.z * inv;
    const float* xd = xdst + 3 * n;
    float d0 = xd[0], d1 = xd[1], d2 = xd[2];
    float r[4];
#pragma unroll
    for (int cc = 0; cc < 4; cc++) {
        int c = c0 + cc;
        float v = sb[c];
        v = fmaf(m0, swl[c * 3 + 0], v);
        v = fmaf(m1, swl[c * 3 + 1], v);
        v = fmaf(m2, swl[c * 3 + 2], v);
        v = fmaf(d0, swr[c * 3 + 0], v);
        v = fmaf(d1, swr[c * 3 + 1], v);
        v = fmaf(d2, swr[c * 3 + 2], v);
        r[cc] = fmaxf(v, 0.0f);
    }
    *reinterpret_cast<float4*>(&g_xp[n * 100 + c0]) =
        make_float4(r[0], r[1], r[2], r[3]);
}

// ---------------- conv (k=2, 100->100) with packed f32x2 ----------------
#define CONV_SMEM ((100 * 202 + 100 * 68) * 4)
__global__ __launch_bounds__(200)
void conv_kernel(const float* __restrict__ in, const float* __restrict__ W,
                 float* __restrict__ out, int Lin, int Lout) {
    extern __shared__ float sm[];
    float* ws = sm;               // [o][202]
    float* xs = sm + 100 * 202;   // [i][68]
    int b  = blockIdx.x;
    int h0 = blockIdx.y << 6;
    int t  = threadIdx.x;

    for (int idx = t; idx < 20000; idx += 200) {
        int o = idx / 200;
        ws[o * 202 + (idx - o * 200)] = W[idx];
    }
    int nj = Lin - h0; if (nj > 65) nj = 65;
    const float* inb = in + b * 100 * Lin + h0;
    for (int idx = t; idx < 6800; idx += 200) {
        int i = idx / 68;
        int j = idx - i * 68;
        xs[idx] = (j < nj) ? inb[i * Lin + j] : 0.0f;
    }
    __syncthreads();

    int og = t >> 3, ht = t & 7;
    int o0 = og << 2, hh = ht << 3;
    double acc2[4][8];
#pragma unroll
    for (int oo = 0; oo < 4; oo++)
#pragma unroll
        for (int j = 0; j < 8; j++) acc2[oo][j] = 0.0;

    for (int i = 0; i < 100; i++) {
        const float* xr = xs + i * 68 + hh;
        float4 xA = *reinterpret_cast<const float4*>(xr);
        float4 xB = *reinterpret_cast<const float4*>(xr + 4);
        float x8 = xr[8];
        double xp[8];
        xp[0] = pk2(xA.x, xA.y); xp[1] = pk2(xA.y, xA.z);
        xp[2] = pk2(xA.z, xA.w); xp[3] = pk2(xA.w, xB.x);
        xp[4] = pk2(xB.x, xB.y); xp[5] = pk2(xB.y, xB.z);
        xp[6] = pk2(xB.z, xB.w); xp[7] = pk2(xB.w, x8);
#pragma unroll
        for (int oo = 0; oo < 4; oo++) {
            double wp = *reinterpret_cast<const double*>(&ws[(o0 + oo) * 202 + i * 2]);
#pragma unroll
            for (int j = 0; j < 8; j++)
                acc2[oo][j] = ffma2(wp, xp[j], acc2[oo][j]);
        }
    }

    float* outb = out + b * 100 * Lout;
#pragma unroll
    for (int oo = 0; oo < 4; oo++)
#pragma unroll
        for (int j = 0; j < 8; j++) {
            int h = h0 + hh + j;
            if (h < Lout) {
                float lo, hi; upk2(acc2[oo][j], lo, hi);
                outb[(o0 + oo) * Lout + h] = fmaxf(lo + hi, 0.0f);
            }
        }
}

// ---------------- dense1: W streamed ONCE, warp = 4o x 16b, f32x2 ----------------
// grid (400 k-chunks, 16 o-tiles). block 256 = 8 warps. Lanes split k.
#define D1_SMEM (16 * 1024 * 4)
__global__ __launch_bounds__(256)
void dense1_kernel(const float* __restrict__ x2, const float* __restrict__ W) {
    extern __shared__ float xs[];   // [16][1024]
    int t = threadIdx.x;
    int k0 = blockIdx.x << 10;
    int KN = KDIM - k0; if (KN > 1024) KN = 1024;   // 1024 or 824, both %4==0

    for (int idx = t; idx < 4096; idx += 256) {
        int b = idx >> 8;
        int kk = (idx & 255) << 2;
        float4 v = make_float4(0.f, 0.f, 0.f, 0.f);
        if (kk < KN)
            v = *reinterpret_cast<const float4*>(x2 + (size_t)b * KDIM + k0 + kk);
        *reinterpret_cast<float4*>(&xs[(b << 10) + kk]) = v;
    }
    __syncthreads();

    int wid = t >> 5, lane = t & 31;
    int o0 = (blockIdx.y << 5) + (wid << 2);
    if (o0 >= O1) return;

    double acc2[4][16];
#pragma unroll
    for (int o = 0; o < 4; o++)
#pragma unroll
        for (int b = 0; b < 16; b++) acc2[o][b] = 0.0;

    const float* wrow = W + (size_t)o0 * KDIM + k0;
    for (int kk = lane * 4; kk < KN; kk += 128) {
        double2 w[4];
#pragma unroll
        for (int o = 0; o < 4; o++)
            w[o] = *reinterpret_cast<const double2*>(wrow + (size_t)o * KDIM + kk);
#pragma unroll
        for (int b = 0; b < 16; b++) {
            double2 xv = *reinterpret_cast<const double2*>(&xs[(b << 10) + kk]);
#pragma unroll
            for (int o = 0; o < 4; o++) {
                acc2[o][b] = ffma2(w[o].x, xv.x, acc2[o][b]);
                acc2[o][b] = ffma2(w[o].y, xv.y, acc2[o][b]);
            }
        }
    }

    // collapse packed halves -> 64 floats, index a = o*16 + b
    float s[64];
#pragma unroll
    for (int a = 0; a < 64; a++) {
        float lo, hi; upk2(acc2[a >> 4][a & 15], lo, hi);
        s[a] = lo + hi;
    }
    // halving butterfly: 5 steps, 62 shuffles; lane ends owning outputs {2*lane, 2*lane+1}
    int n = 64;
#pragma unroll
    for (int d = 16; d >= 1; d >>= 1) {
        n >>= 1;
        bool hiSel = (lane & d) != 0;
#pragma unroll
        for (int i = 0; i < 32; i++) {
            if (i >= n) break;
            float send = hiSel ? s[i] : s[i + n];
            float recv = __shfl_xor_sync(0xffffffffu, send, d);
            float keep = hiSel ? s[i + n] : s[i];
            s[i] = keep + recv;
        }
    }
    int a0 = 2 * lane;                       // even -> b even, same o for a0,a0+1
    float* addr = &g_y1[(o0 + (a0 >> 4)) * 16 + (a0 & 15)];
    asm volatile("red.global.add.v2.f32 [%0], {%1, %2};"
                 :: "l"(addr), "f"(s[0]), "f"(s[1]) : "memory");
}

// ---------------- dense2 + softmax ----------------
__global__ void dense2_kernel(const float* __restrict__ Wd2, float* __restrict__ out) {
    __shared__ float ys[O1];
    __shared__ float red[128];
    int b = blockIdx.x, t = threadIdx.x;
    for (int o = t; o < O1; o += 128) ys[o] = fmaxf(g_y1[o * 16 + b], 0.0f);
    __syncthreads();

    float logit = -1e30f;
    if (t < NCLS) {
        float s = 0.0f;
        const float* wr = Wd2 + t * O1;
        for (int o = 0; o < O1; o++) s = fmaf(ys[o], __ldg(wr + o), s);
        logit = s;
    }
    red[t] = logit;
    __syncthreads();
    for (int s = 64; s > 0; s >>= 1) {
        if (t < s) red[t] = fmaxf(red[t], red[t + s]);
        __syncthreads();
    }
    float mx = red[0];
    __syncthreads();
    float e = (t < NCLS) ? expf(logit - mx) : 0.0f;
    red[t] = e;
    __syncthreads();
    for (int s = 64; s > 0; s >>= 1) {
        if (t < s) red[t] += red[t + s];
        __syncthreads();
    }
    float sum = red[0];
    if (t < NCLS) out[b * NCLS + t] = e / sum;
}

// ---------------- launch ----------------
extern "C" void kernel_launch(void* const* d_in, const int* in_sizes, int n_in,
                              void* d_out, int out_size) {
    const float* x_src = (const float*)d_in[0];
    const float* x_dst = (const float*)d_in[1];
    const int*   ei    = (const int*)  d_in[2];
    const float* Wfd   = (const float*)d_in[3];
    const float* bfd   = (const float*)d_in[4];
    const float* Wl1   = (const float*)d_in[5];
    const float* bl1   = (const float*)d_in[6];
    const float* Wr1   = (const float*)d_in[7];
    // d_in[8..10] dead (second GNN layer output unused by reference)
    const float* Wc1   = (const float*)d_in[11];
    const float* Wc2   = (const float*)d_in[12];
    const float* Wd1   = (const float*)d_in[13];
    const float* Wd2   = (const float*)d_in[14];
    float* out = (float*)d_out;

    float *p_xp, *p_o1, *p_o2;
    cudaGetSymbolAddress((void**)&p_xp, g_xp);
    cudaGetSymbolAddress((void**)&p_o1, g_out1);
    cudaGetSymbolAddress((void**)&p_o2, g_out2);

    cudaFuncSetAttribute(feat_kernel,  cudaFuncAttributeMaxDynamicSharedMemorySize, FEAT_SMEM);
    cudaFuncSetAttribute(conv_kernel,  cudaFuncAttributeMaxDynamicSharedMemorySize, CONV_SMEM);
    cudaFuncSetAttribute(dense1_kernel, cudaFuncAttributeMaxDynamicSharedMemorySize, D1_SMEM);

    zero_kernel<<<(N_P * 4 + 255) / 256, 256>>>();
    feat_kernel<<<128, 256, FEAT_SMEM>>>(x_src, Wfd, bfd);
    edge_kernel<<<4096, 256>>>(ei);
    node_kernel<<<6400, 256>>>(x_dst, Wl1, bl1, Wr1);
    conv_kernel<<<dim3(16, 64), 200, CONV_SMEM>>>(p_xp, Wc1, p_o1, L0, L1V);
    conv_kernel<<<dim3(16, 64), 200, CONV_SMEM>>>(p_o1, Wc2, p_o2, L1V, L2V);
    dense1_kernel<<<dim3(400, 16), 256, D1_SMEM>>>(p_o2, Wd1);
    dense2_kernel<<<NB, 128>>>(Wd2, out);
}

// round 5
// speedup vs baseline: 1.8632x; 1.1307x over previous
#include <cuda_runtime.h>
#include <cstdint>

// ---------------- problem constants ----------------
#define NB       16
#define N_F      524288
#define N_P      65536
#define EH       2097152
#define E_TOTAL  4194304
#define XP_N     6553600
#define L0       4096
#define L1V      4095
#define L2V      4094
#define KDIM     409400
#define O1       500
#define NCLS     107

// ---------------- packed fp32x2 helpers ----------------
__device__ __forceinline__ double pk2(float lo, float hi) {
    double d; asm("mov.b64 %0, {%1, %2};" : "=d"(d) : "f"(lo), "f"(hi)); return d;
}
__device__ __forceinline__ void upk2(double d, float& lo, float& hi) {
    asm("mov.b64 {%0, %1}, %2;" : "=f"(lo), "=f"(hi) : "d"(d));
}
__device__ __forceinline__ double ffma2(double a, double b, double c) {
    double d; asm("fma.rn.f32x2 %0, %1, %2, %3;" : "=d"(d) : "d"(a), "d"(b), "d"(c)); return d;
}
// packed fp32 pairwise add (NOT fp64 add!)
__device__ __forceinline__ double fadd2(double a, double b) {
    double d; asm("add.rn.f32x2 %0, %1, %2;" : "=d"(d) : "d"(a), "d"(b)); return d;
}

// ---------------- scratch ----------------
__device__ float4 g_xf4[N_F];
__device__ float g_agg[N_P * 4];
__device__ float g_xp[XP_N];
__device__ float g_out1[NB * 100 * L1V];
__device__ float g_out2[NB * 100 * L2V];
__device__ float g_y1[O1 * NB];

// ---------------- zero init ----------------
__global__ void zero_kernel() {
    int i = blockIdx.x * 256 + threadIdx.x;
    if (i < N_P * 4) g_agg[i] = 0.0f;
    if (i < O1 * NB) g_y1[i] = 0.0f;
}

// ---------------- feat: 8192x64 @ 64x192 -> g_xf4 ----------------
#define FEAT_SMEM ((64 * 65 + 192 * 65) * 4)
__global__ __launch_bounds__(256)
void feat_kernel(const float* __restrict__ xsrc,
                 const float* __restrict__ Wfd,
                 const float* __restrict__ bfd) {
    extern __shared__ float sm[];
    float* xs = sm;             // [64][65]
    float* ws = sm + 64 * 65;   // [192][65]
    int t = threadIdx.x;
    int i0 = blockIdx.x << 6;

    for (int idx = t; idx < 4096; idx += 256) {
        int i = idx >> 6, k = idx & 63;
        xs[i * 65 + k] = xsrc[(i0 + i) * 64 + k];
    }
    for (int idx = t; idx < 12288; idx += 256) {
        int j = idx >> 6, k = idx & 63;
        ws[j * 65 + k] = Wfd[idx];
    }
    __syncthreads();

    int tx = t & 15, ty = t >> 4;
    float acc[4][12];
#pragma unroll
    for (int ii = 0; ii < 4; ii++)
#pragma unroll
        for (int jj = 0; jj < 12; jj++) acc[ii][jj] = 0.0f;

    for (int k = 0; k < 64; k++) {
        float xv[4], wv[12];
#pragma unroll
        for (int ii = 0; ii < 4; ii++) xv[ii] = xs[(ty * 4 + ii) * 65 + k];
#pragma unroll
        for (int jj = 0; jj < 12; jj++) wv[jj] = ws[(tx * 12 + jj) * 65 + k];
#pragma unroll
        for (int ii = 0; ii < 4; ii++)
#pragma unroll
            for (int jj = 0; jj < 12; jj++)
                acc[ii][jj] = fmaf(xv[ii], wv[jj], acc[ii][jj]);
    }

    int j0 = tx * 12;
#pragma unroll
    for (int ii = 0; ii < 4; ii++) {
        int i = i0 + ty * 4 + ii;
#pragma unroll
        for (int rr = 0; rr < 4; rr++) {
            int r = i * 64 + tx * 4 + rr;
            g_xf4[r] = make_float4(
                acc[ii][rr * 3 + 0] + __ldg(bfd + j0 + rr * 3 + 0),
                acc[ii][rr * 3 + 1] + __ldg(bfd + j0 + rr * 3 + 1),
                acc[ii][rr * 3 + 2] + __ldg(bfd + j0 + rr * 3 + 2),
                0.0f);
        }
    }
}

// ---------------- edge aggregation ----------------
__global__ void edge_kernel(const int* __restrict__ ei) {
    int e2 = blockIdx.x * 256 + threadIdx.x;
    int4 s4 = *reinterpret_cast<const int4*>(ei + 4 * e2);
    int4 d4 = *reinterpret_cast<const int4*>(ei + E_TOTAL + 4 * e2);
    float4 v0 = g_xf4[s4.x];
    float4 v1 = g_xf4[s4.z];
    float* a0 = g_agg + 4 * d4.x;
    float* a1 = g_agg + 4 * d4.z;
    asm volatile("red.global.add.v4.f32 [%0], {%1, %2, %3, %4};"
                 :: "l"(a0), "f"(v0.x), "f"(v0.y), "f"(v0.z), "f"(1.0f) : "memory");
    asm volatile("red.global.add.v4.f32 [%0], {%1, %2, %3, %4};"
                 :: "l"(a1), "f"(v1.x), "f"(v1.y), "f"(v1.z), "f"(1.0f) : "memory");
}

// ---------------- node update ----------------
__global__ __launch_bounds__(256)
void node_kernel(const float* __restrict__ xdst,
                 const float* __restrict__ Wl1,
                 const float* __restrict__ bl1,
                 const float* __restrict__ Wr1) {
    __shared__ float swl[300], swr[300], sb[100];
    int t = threadIdx.x;
    for (int idx = t; idx < 300; idx += 256) { swl[idx] = Wl1[idx]; swr[idx] = Wr1[idx]; }
    if (t < 100) sb[t] = bl1[t];
    __syncthreads();

    int gid = blockIdx.x * 256 + t;
    int n = gid / 25;
    int c0 = (gid - n * 25) * 4;
    float4 a = *reinterpret_cast<const float4*>(&g_agg[n * 4]);
    float inv = __fdividef(1.0f, fmaxf(a.w, 1.0f));
    float m0 = a.x * inv, m1 = a.y * inv, m2 = a.z * inv;
    const float* xd = xdst + 3 * n;
    float d0 = xd[0], d1 = xd[1], d2 = xd[2];
    float r[4];
#pragma unroll
    for (int cc = 0; cc < 4; cc++) {
        int c = c0 + cc;
        float v = sb[c];
        v = fmaf(m0, swl[c * 3 + 0], v);
        v = fmaf(m1, swl[c * 3 + 1], v);
        v = fmaf(m2, swl[c * 3 + 2], v);
        v = fmaf(d0, swr[c * 3 + 0], v);
        v = fmaf(d1, swr[c * 3 + 1], v);
        v = fmaf(d2, swr[c * 3 + 2], v);
        r[cc] = fmaxf(v, 0.0f);
    }
    *reinterpret_cast<float4*>(&g_xp[n * 100 + c0]) =
        make_float4(r[0], r[1], r[2], r[3]);
}

// ---------------- conv (k=2, 100->100), packed f32x2 over k-pairs ----------------
#define CONV_SMEM ((100 * 202 + 100 * 68) * 4)
__global__ __launch_bounds__(200)
void conv_kernel(const float* __restrict__ in, const float* __restrict__ W,
                 float* __restrict__ out, int Lin, int Lout) {
    extern __shared__ float sm[];
    float* ws = sm;               // [o][202]
    float* xs = sm + 100 * 202;   // [i][68]
    int b  = blockIdx.x;
    int h0 = blockIdx.y << 6;
    int t  = threadIdx.x;

    for (int idx = t; idx < 20000; idx += 200) {
        int o = idx / 200;
        ws[o * 202 + (idx - o * 200)] = W[idx];
    }
    int nj = Lin - h0; if (nj > 65) nj = 65;
    const float* inb = in + b * 100 * Lin + h0;
    for (int idx = t; idx < 6800; idx += 200) {
        int i = idx / 68;
        int j = idx - i * 68;
        xs[idx] = (j < nj) ? inb[i * Lin + j] : 0.0f;
    }
    __syncthreads();

    int og = t >> 3, ht = t & 7;
    int o0 = og << 2, hh = ht << 3;
    double acc2[4][8];
#pragma unroll
    for (int oo = 0; oo < 4; oo++)
#pragma unroll
        for (int j = 0; j < 8; j++) acc2[oo][j] = 0.0;

    for (int i = 0; i < 100; i++) {
        const float* xr = xs + i * 68 + hh;
        float4 xA = *reinterpret_cast<const float4*>(xr);
        float4 xB = *reinterpret_cast<const float4*>(xr + 4);
        float x8 = xr[8];
        double xp[8];
        xp[0] = pk2(xA.x, xA.y); xp[1] = pk2(xA.y, xA.z);
        xp[2] = pk2(xA.z, xA.w); xp[3] = pk2(xA.w, xB.x);
        xp[4] = pk2(xB.x, xB.y); xp[5] = pk2(xB.y, xB.z);
        xp[6] = pk2(xB.z, xB.w); xp[7] = pk2(xB.w, x8);
#pragma unroll
        for (int oo = 0; oo < 4; oo++) {
            double wp = *reinterpret_cast<const double*>(&ws[(o0 + oo) * 202 + i * 2]);
#pragma unroll
            for (int j = 0; j < 8; j++)
                acc2[oo][j] = ffma2(wp, xp[j], acc2[oo][j]);
        }
    }

    float* outb = out + b * 100 * Lout;
#pragma unroll
    for (int oo = 0; oo < 4; oo++)
#pragma unroll
        for (int j = 0; j < 8; j++) {
            int h = h0 + hh + j;
            if (h < Lout) {
                float lo, hi; upk2(acc2[oo][j], lo, hi);
                outb[(o0 + oo) * Lout + h] = fmaxf(lo + hi, 0.0f);
            }
        }
}

// ---------------- dense1: b-pair packed accumulators, lane = k, 2 blocks/SM ------
// grid (400 k-chunks, 16 o-tiles). block 256 = 8 warps x 4 o.
// xs transposed: [k][b] rows of 20 floats (pad 16->20: conflict-free LDS.128).
#define D1_SMEM (1024 * 20 * 4)
__global__ __launch_bounds__(256, 2)
void dense1_kernel(const float* __restrict__ x2, const float* __restrict__ W) {
    extern __shared__ float xs[];   // [1024][20]
    int t = threadIdx.x;
    int k0 = blockIdx.x << 10;
    int KN = KDIM - k0; if (KN > 1024) KN = 1024;

    for (int idx = t; idx < 4096; idx += 256) {
        int b = idx >> 8;
        int kk = (idx & 255) << 2;
        float4 v = make_float4(0.f, 0.f, 0.f, 0.f);
        if (kk < KN)
            v = *reinterpret_cast<const float4*>(x2 + (size_t)b * KDIM + k0 + kk);
        xs[(kk + 0) * 20 + b] = v.x;
        xs[(kk + 1) * 20 + b] = v.y;
        xs[(kk + 2) * 20 + b] = v.z;
        xs[(kk + 3) * 20 + b] = v.w;
    }
    __syncthreads();

    int wid = t >> 5, lane = t & 31;
    int o0 = (blockIdx.y << 5) + (wid << 2);
    if (o0 >= O1) return;

    double acc2[4][8];   // [o][b-pair], packed fp32x2
#pragma unroll
    for (int o = 0; o < 4; o++)
#pragma unroll
        for (int bp = 0; bp < 8; bp++) acc2[o][bp] = 0.0;

    const float* wbase = W + (size_t)o0 * KDIM + k0;
#pragma unroll 2
    for (int it = 0; it < 32; it++) {
        int k = lane + (it << 5);
        float wv[4];
#pragma unroll
        for (int o = 0; o < 4; o++)
            wv[o] = (k < KN) ? __ldg(wbase + (size_t)o * KDIM + k) : 0.0f;
        double wd[4];
#pragma unroll
        for (int o = 0; o < 4; o++) wd[o] = pk2(wv[o], wv[o]);

        const float* xrow = &xs[k * 20];
        double xp[8];
#pragma unroll
        for (int q = 0; q < 4; q++) {
            float4 v = reinterpret_cast<const float4*>(xrow)[q];
            xp[2 * q]     = pk2(v.x, v.y);
            xp[2 * q + 1] = pk2(v.z, v.w);
        }
#pragma unroll
        for (int o = 0; o < 4; o++)
#pragma unroll
            for (int bp = 0; bp < 8; bp++)
                acc2[o][bp] = ffma2(wd[o], xp[bp], acc2[o][bp]);
    }

    // halving butterfly on 32 packed pairs; PACKED add (add.rn.f32x2), not fp64 +
    double s2[32];
#pragma unroll
    for (int a = 0; a < 32; a++) s2[a] = acc2[a >> 3][a & 7];
    int n = 32;
#pragma unroll
    for (int d = 16; d >= 1; d >>= 1) {
        n >>= 1;
        bool hiSel = (lane & d) != 0;
#pragma unroll
        for (int i = 0; i < 16; i++) {
            if (i >= n) break;
            double send = hiSel ? s2[i] : s2[i + n];
            double recv = __shfl_xor_sync(0xffffffffu, send, d);
            double keep = hiSel ? s2[i + n] : s2[i];
            s2[i] = fadd2(keep, recv);
        }
    }
    float lo, hi; upk2(s2[0], lo, hi);
    float* addr = &g_y1[(o0 + (lane >> 3)) * 16 + 2 * (lane & 7)];
    asm volatile("red.global.add.v2.f32 [%0], {%1, %2};"
                 :: "l"(addr), "f"(lo), "f"(hi) : "memory");
}

// ---------------- dense2 + softmax ----------------
__global__ void dense2_kernel(const float* __restrict__ Wd2, float* __restrict__ out) {
    __shared__ float ys[O1];
    __shared__ float red[128];
    int b = blockIdx.x, t = threadIdx.x;
    for (int o = t; o < O1; o += 128) ys[o] = fmaxf(g_y1[o * 16 + b], 0.0f);
    __syncthreads();

    float logit = -1e30f;
    if (t < NCLS) {
        float s = 0.0f;
        const float* wr = Wd2 + t * O1;
        for (int o = 0; o < O1; o++) s = fmaf(ys[o], __ldg(wr + o), s);
        logit = s;
    }
    red[t] = logit;
    __syncthreads();
    for (int s = 64; s > 0; s >>= 1) {
        if (t < s) red[t] = fmaxf(red[t], red[t + s]);
        __syncthreads();
    }
    float mx = red[0];
    __syncthreads();
    float e = (t < NCLS) ? expf(logit - mx) : 0.0f;
    red[t] = e;
    __syncthreads();
    for (int s = 64; s > 0; s >>= 1) {
        if (t < s) red[t] += red[t + s];
        __syncthreads();
    }
    float sum = red[0];
    if (t < NCLS) out[b * NCLS + t] = e / sum;
}

// ---------------- launch ----------------
extern "C" void kernel_launch(void* const* d_in, const int* in_sizes, int n_in,
                              void* d_out, int out_size) {
    const float* x_src = (const float*)d_in[0];
    const float* x_dst = (const float*)d_in[1];
    const int*   ei    = (const int*)  d_in[2];
    const float* Wfd   = (const float*)d_in[3];
    const float* bfd   = (const float*)d_in[4];
    const float* Wl1   = (const float*)d_in[5];
    const float* bl1   = (const float*)d_in[6];
    const float* Wr1   = (const float*)d_in[7];
    const float* Wc1   = (const float*)d_in[11];
    const float* Wc2   = (const float*)d_in[12];
    const float* Wd1   = (const float*)d_in[13];
    const float* Wd2   = (const float*)d_in[14];
    float* out = (float*)d_out;

    float *p_xp, *p_o1, *p_o2;
    cudaGetSymbolAddress((void**)&p_xp, g_xp);
    cudaGetSymbolAddress((void**)&p_o1, g_out1);
    cudaGetSymbolAddress((void**)&p_o2, g_out2);

    cudaFuncSetAttribute(feat_kernel,   cudaFuncAttributeMaxDynamicSharedMemorySize, FEAT_SMEM);
    cudaFuncSetAttribute(conv_kernel,   cudaFuncAttributeMaxDynamicSharedMemorySize, CONV_SMEM);
    cudaFuncSetAttribute(dense1_kernel, cudaFuncAttributeMaxDynamicSharedMemorySize, D1_SMEM);

    zero_kernel<<<(N_P * 4 + 255) / 256, 256>>>();
    feat_kernel<<<128, 256, FEAT_SMEM>>>(x_src, Wfd, bfd);
    edge_kernel<<<4096, 256>>>(ei);
    node_kernel<<<6400, 256>>>(x_dst, Wl1, bl1, Wr1);
    conv_kernel<<<dim3(16, 64), 200, CONV_SMEM>>>(p_xp, Wc1, p_o1, L0, L1V);
    conv_kernel<<<dim3(16, 64), 200, CONV_SMEM>>>(p_o1, Wc2, p_o2, L1V, L2V);
    dense1_kernel<<<dim3(400, 16), 256, D1_SMEM>>>(p_o2, Wd1);
    dense2_kernel<<<NB, 128>>>(Wd2, out);
}

// round 6
// speedup vs baseline: 2.0374x; 1.0935x over previous
#include <cuda_runtime.h>
#include <cstdint>

// ---------------- problem constants ----------------
#define NB       16
#define N_F      524288
#define N_P      65536
#define EH       2097152
#define E_TOTAL  4194304
#define XP_N     6553600
#define L0       4096
#define L1V      4095
#define L2V      4094
#define KDIM     409400
#define O1       500
#define NCLS     107

// ---------------- packed fp32x2 helpers ----------------
__device__ __forceinline__ double pk2(float lo, float hi) {
    double d; asm("mov.b64 %0, {%1, %2};" : "=d"(d) : "f"(lo), "f"(hi)); return d;
}
__device__ __forceinline__ void upk2(double d, float& lo, float& hi) {
    asm("mov.b64 {%0, %1}, %2;" : "=f"(lo), "=f"(hi) : "d"(d));
}
__device__ __forceinline__ double ffma2(double a, double b, double c) {
    double d; asm("fma.rn.f32x2 %0, %1, %2, %3;" : "=d"(d) : "d"(a), "d"(b), "d"(c)); return d;
}
__device__ __forceinline__ double fadd2(double a, double b) {
    double d; asm("add.rn.f32x2 %0, %1, %2;" : "=d"(d) : "d"(a), "d"(b)); return d;
}

// ---------------- scratch ----------------
__device__ float4 g_xf4[N_F];
__device__ float g_agg[N_P * 4];
__device__ float g_xp[XP_N];
__device__ float g_out1[NB * 100 * L1V];
__device__ float g_out2[NB * 100 * L2V];
__device__ float g_y1[O1 * NB];

// ---------------- zero init ----------------
__global__ void zero_kernel() {
    int i = blockIdx.x * 256 + threadIdx.x;
    if (i < N_P * 4) g_agg[i] = 0.0f;
    if (i < O1 * NB) g_y1[i] = 0.0f;
}

// ---------------- feat: 8192x64 @ 64x192 -> g_xf4 ----------------
#define FEAT_SMEM ((64 * 65 + 192 * 65) * 4)
__global__ __launch_bounds__(256)
void feat_kernel(const float* __restrict__ xsrc,
                 const float* __restrict__ Wfd,
                 const float* __restrict__ bfd) {
    extern __shared__ float sm[];
    float* xs = sm;             // [64][65]
    float* ws = sm + 64 * 65;   // [192][65]
    int t = threadIdx.x;
    int i0 = blockIdx.x << 6;

    for (int idx = t; idx < 4096; idx += 256) {
        int i = idx >> 6, k = idx & 63;
        xs[i * 65 + k] = xsrc[(i0 + i) * 64 + k];
    }
    for (int idx = t; idx < 12288; idx += 256) {
        int j = idx >> 6, k = idx & 63;
        ws[j * 65 + k] = Wfd[idx];
    }
    __syncthreads();

    int tx = t & 15, ty = t >> 4;
    float acc[4][12];
#pragma unroll
    for (int ii = 0; ii < 4; ii++)
#pragma unroll
        for (int jj = 0; jj < 12; jj++) acc[ii][jj] = 0.0f;

    for (int k = 0; k < 64; k++) {
        float xv[4], wv[12];
#pragma unroll
        for (int ii = 0; ii < 4; ii++) xv[ii] = xs[(ty * 4 + ii) * 65 + k];
#pragma unroll
        for (int jj = 0; jj < 12; jj++) wv[jj] = ws[(tx * 12 + jj) * 65 + k];
#pragma unroll
        for (int ii = 0; ii < 4; ii++)
#pragma unroll
            for (int jj = 0; jj < 12; jj++)
                acc[ii][jj] = fmaf(xv[ii], wv[jj], acc[ii][jj]);
    }

    int j0 = tx * 12;
#pragma unroll
    for (int ii = 0; ii < 4; ii++) {
        int i = i0 + ty * 4 + ii;
#pragma unroll
        for (int rr = 0; rr < 4; rr++) {
            int r = i * 64 + tx * 4 + rr;
            g_xf4[r] = make_float4(
                acc[ii][rr * 3 + 0] + __ldg(bfd + j0 + rr * 3 + 0),
                acc[ii][rr * 3 + 1] + __ldg(bfd + j0 + rr * 3 + 1),
                acc[ii][rr * 3 + 2] + __ldg(bfd + j0 + rr * 3 + 2),
                0.0f);
        }
    }
}

// ---------------- edge aggregation ----------------
__global__ void edge_kernel(const int* __restrict__ ei) {
    int e2 = blockIdx.x * 256 + threadIdx.x;
    int4 s4 = *reinterpret_cast<const int4*>(ei + 4 * e2);
    int4 d4 = *reinterpret_cast<const int4*>(ei + E_TOTAL + 4 * e2);
    float4 v0 = g_xf4[s4.x];
    float4 v1 = g_xf4[s4.z];
    float* a0 = g_agg + 4 * d4.x;
    float* a1 = g_agg + 4 * d4.z;
    asm volatile("red.global.add.v4.f32 [%0], {%1, %2, %3, %4};"
                 :: "l"(a0), "f"(v0.x), "f"(v0.y), "f"(v0.z), "f"(1.0f) : "memory");
    asm volatile("red.global.add.v4.f32 [%0], {%1, %2, %3, %4};"
                 :: "l"(a1), "f"(v1.x), "f"(v1.y), "f"(v1.z), "f"(1.0f) : "memory");
}

// ---------------- node update ----------------
__global__ __launch_bounds__(256)
void node_kernel(const float* __restrict__ xdst,
                 const float* __restrict__ Wl1,
                 const float* __restrict__ bl1,
                 const float* __restrict__ Wr1) {
    __shared__ float swl[300], swr[300], sb[100];
    int t = threadIdx.x;
    for (int idx = t; idx < 300; idx += 256) { swl[idx] = Wl1[idx]; swr[idx] = Wr1[idx]; }
    if (t < 100) sb[t] = bl1[t];
    __syncthreads();

    int gid = blockIdx.x * 256 + t;
    int n = gid / 25;
    int c0 = (gid - n * 25) * 4;
    float4 a = *reinterpret_cast<const float4*>(&g_agg[n * 4]);
    float inv = __fdividef(1.0f, fmaxf(a.w, 1.0f));
    float m0 = a.x * inv, m1 = a.y * inv, m2 = a.z * inv;
    const float* xd = xdst + 3 * n;
    float d0 = xd[0], d1 = xd[1], d2 = xd[2];
    float r[4];
#pragma unroll
    for (int cc = 0; cc < 4; cc++) {
        int c = c0 + cc;
        float v = sb[c];
        v = fmaf(m0, swl[c * 3 + 0], v);
        v = fmaf(m1, swl[c * 3 + 1], v);
        v = fmaf(m2, swl[c * 3 + 2], v);
        v = fmaf(d0, swr[c * 3 + 0], v);
        v = fmaf(d1, swr[c * 3 + 1], v);
        v = fmaf(d2, swr[c * 3 + 2], v);
        r[cc] = fmaxf(v, 0.0f);
    }
    *reinterpret_cast<float4*>(&g_xp[n * 100 + c0]) =
        make_float4(r[0], r[1], r[2], r[3]);
}

// ---------------- conv (k=2, 100->100), packed f32x2 over k-pairs ----------------
#define CONV_SMEM ((100 * 202 + 100 * 68) * 4)
__global__ __launch_bounds__(200)
void conv_kernel(const float* __restrict__ in, const float* __restrict__ W,
                 float* __restrict__ out, int Lin, int Lout) {
    extern __shared__ float sm[];
    float* ws = sm;               // [o][202]
    float* xs = sm + 100 * 202;   // [i][68]
    int b  = blockIdx.x;
    int h0 = blockIdx.y << 6;
    int t  = threadIdx.x;

    for (int idx = t; idx < 20000; idx += 200) {
        int o = idx / 200;
        ws[o * 202 + (idx - o * 200)] = W[idx];
    }
    int nj = Lin - h0; if (nj > 65) nj = 65;
    const float* inb = in + b * 100 * Lin + h0;
    for (int idx = t; idx < 6800; idx += 200) {
        int i = idx / 68;
        int j = idx - i * 68;
        xs[idx] = (j < nj) ? inb[i * Lin + j] : 0.0f;
    }
    __syncthreads();

    int og = t >> 3, ht = t & 7;
    int o0 = og << 2, hh = ht << 3;
    double acc2[4][8];
#pragma unroll
    for (int oo = 0; oo < 4; oo++)
#pragma unroll
        for (int j = 0; j < 8; j++) acc2[oo][j] = 0.0;

    for (int i = 0; i < 100; i++) {
        const float* xr = xs + i * 68 + hh;
        float4 xA = *reinterpret_cast<const float4*>(xr);
        float4 xB = *reinterpret_cast<const float4*>(xr + 4);
        float x8 = xr[8];
        double xp[8];
        xp[0] = pk2(xA.x, xA.y); xp[1] = pk2(xA.y, xA.z);
        xp[2] = pk2(xA.z, xA.w); xp[3] = pk2(xA.w, xB.x);
        xp[4] = pk2(xB.x, xB.y); xp[5] = pk2(xB.y, xB.z);
        xp[6] = pk2(xB.z, xB.w); xp[7] = pk2(xB.w, x8);
#pragma unroll
        for (int oo = 0; oo < 4; oo++) {
            double wp = *reinterpret_cast<const double*>(&ws[(o0 + oo) * 202 + i * 2]);
#pragma unroll
            for (int j = 0; j < 8; j++)
                acc2[oo][j] = ffma2(wp, xp[j], acc2[oo][j]);
        }
    }

    float* outb = out + b * 100 * Lout;
#pragma unroll
    for (int oo = 0; oo < 4; oo++)
#pragma unroll
        for (int j = 0; j < 8; j++) {
            int h = h0 + hh + j;
            if (h < Lout) {
                float lo, hi; upk2(acc2[oo][j], lo, hi);
                outb[(o0 + oo) * Lout + h] = fmaxf(lo + hi, 0.0f);
            }
        }
}

// ---------------- dense1: 4-deep W prefetch pipeline, b-pair f32x2 accumulators --
// grid (400 k-chunks, 16 o-tiles). block 256 = 8 warps x 4 o. lane = k (stride 32).
// xs transposed: [k][b] rows of 20 floats (conflict-free LDS.128 at k=lane).
#define D1_SMEM (1024 * 20 * 4)
__global__ __launch_bounds__(256, 2)
void dense1_kernel(const float* __restrict__ x2, const float* __restrict__ W) {
    extern __shared__ float xs[];   // [1024][20]
    int t = threadIdx.x;
    int k0 = blockIdx.x << 10;
    int KN = KDIM - k0; if (KN > 1024) KN = 1024;

    for (int idx = t; idx < 4096; idx += 256) {
        int b = idx >> 8;
        int kk = (idx & 255) << 2;
        float4 v = make_float4(0.f, 0.f, 0.f, 0.f);
        if (kk < KN)
            v = *reinterpret_cast<const float4*>(x2 + (size_t)b * KDIM + k0 + kk);
        xs[(kk + 0) * 20 + b] = v.x;
        xs[(kk + 1) * 20 + b] = v.y;
        xs[(kk + 2) * 20 + b] = v.z;
        xs[(kk + 3) * 20 + b] = v.w;
    }
    __syncthreads();

    int wid = t >> 5, lane = t & 31;
    int o0 = (blockIdx.y << 5) + (wid << 2);
    if (o0 >= O1) return;

    double acc2[4][8];   // [o][b-pair], packed fp32x2
#pragma unroll
    for (int o = 0; o < 4; o++)
#pragma unroll
        for (int bp = 0; bp < 8; bp++) acc2[o][bp] = 0.0;

    const float* wbase = W + (size_t)o0 * KDIM + k0;

    // prologue: prefetch iterations 0..3 into circular buffer
    float wbuf[4][4];
#pragma unroll
    for (int p = 0; p < 4; p++) {
        int k = lane + (p << 5);
#pragma unroll
        for (int o = 0; o < 4; o++)
            wbuf[p][o] = (k < KN) ? __ldg(wbase + (size_t)o * KDIM + k) : 0.0f;
    }

#pragma unroll 4
    for (int it = 0; it < 32; it++) {
        int slot = it & 3;
        float wv[4];
#pragma unroll
        for (int o = 0; o < 4; o++) wv[o] = wbuf[slot][o];

        // refill slot with iteration it+4 (dependency distance = 4 iters)
        int kn = lane + ((it + 4) << 5);
#pragma unroll
        for (int o = 0; o < 4; o++)
            wbuf[slot][o] = (kn < KN) ? __ldg(wbase + (size_t)o * KDIM + kn) : 0.0f;

        int k = lane + (it << 5);
        const float* xrow = &xs[k * 20];
        double xp[8];
#pragma unroll
        for (int q = 0; q < 4; q++) {
            float4 v = reinterpret_cast<const float4*>(xrow)[q];
            xp[2 * q]     = pk2(v.x, v.y);
            xp[2 * q + 1] = pk2(v.z, v.w);
        }
        double wd[4];
#pragma unroll
        for (int o = 0; o < 4; o++) wd[o] = pk2(wv[o], wv[o]);
#pragma unroll
        for (int o = 0; o < 4; o++)
#pragma unroll
            for (int bp = 0; bp < 8; bp++)
                acc2[o][bp] = ffma2(wd[o], xp[bp], acc2[o][bp]);
    }

    // halving butterfly on 32 packed pairs with packed adds
    double s2[32];
#pragma unroll
    for (int a = 0; a < 32; a++) s2[a] = acc2[a >> 3][a & 7];
    int n = 32;
#pragma unroll
    for (int d = 16; d >= 1; d >>= 1) {
        n >>= 1;
        bool hiSel = (lane & d) != 0;
#pragma unroll
        for (int i = 0; i < 16; i++) {
            if (i >= n) break;
            double send = hiSel ? s2[i] : s2[i + n];
            double recv = __shfl_xor_sync(0xffffffffu, send, d);
            double keep = hiSel ? s2[i + n] : s2[i];
            s2[i] = fadd2(keep, recv);
        }
    }
    float lo, hi; upk2(s2[0], lo, hi);
    float* addr = &g_y1[(o0 + (lane >> 3)) * 16 + 2 * (lane & 7)];
    asm volatile("red.global.add.v2.f32 [%0], {%1, %2};"
                 :: "l"(addr), "f"(lo), "f"(hi) : "memory");
}

// ---------------- dense2 + softmax ----------------
__global__ void dense2_kernel(const float* __restrict__ Wd2, float* __restrict__ out) {
    __shared__ float ys[O1];
    __shared__ float red[128];
    int b = blockIdx.x, t = threadIdx.x;
    for (int o = t; o < O1; o += 128) ys[o] = fmaxf(g_y1[o * 16 + b], 0.0f);
    __syncthreads();

    float logit = -1e30f;
    if (t < NCLS) {
        float s = 0.0f;
        const float* wr = Wd2 + t * O1;
        for (int o = 0; o < O1; o++) s = fmaf(ys[o], __ldg(wr + o), s);
        logit = s;
    }
    red[t] = logit;
    __syncthreads();
    for (int s = 64; s > 0; s >>= 1) {
        if (t < s) red[t] = fmaxf(red[t], red[t + s]);
        __syncthreads();
    }
    float mx = red[0];
    __syncthreads();
    float e = (t < NCLS) ? expf(logit - mx) : 0.0f;
    red[t] = e;
    __syncthreads();
    for (int s = 64; s > 0; s >>= 1) {
        if (t < s) red[t] += red[t + s];
        __syncthreads();
    }
    float sum = red[0];
    if (t < NCLS) out[b * NCLS + t] = e / sum;
}

// ---------------- launch ----------------
extern "C" void kernel_launch(void* const* d_in, const int* in_sizes, int n_in,
                              void* d_out, int out_size) {
    const float* x_src = (const float*)d_in[0];
    const float* x_dst = (const float*)d_in[1];
    const int*   ei    = (const int*)  d_in[2];
    const float* Wfd   = (const float*)d_in[3];
    const float* bfd   = (const float*)d_in[4];
    const float* Wl1   = (const float*)d_in[5];
    const float* bl1   = (const float*)d_in[6];
    const float* Wr1   = (const float*)d_in[7];
    const float* Wc1   = (const float*)d_in[11];
    const float* Wc2   = (const float*)d_in[12];
    const float* Wd1   = (const float*)d_in[13];
    const float* Wd2   = (const float*)d_in[14];
    float* out = (float*)d_out;

    float *p_xp, *p_o1, *p_o2;
    cudaGetSymbolAddress((void**)&p_xp, g_xp);
    cudaGetSymbolAddress((void**)&p_o1, g_out1);
    cudaGetSymbolAddress((void**)&p_o2, g_out2);

    cudaFuncSetAttribute(feat_kernel,   cudaFuncAttributeMaxDynamicSharedMemorySize, FEAT_SMEM);
    cudaFuncSetAttribute(conv_kernel,   cudaFuncAttributeMaxDynamicSharedMemorySize, CONV_SMEM);
    cudaFuncSetAttribute(dense1_kernel, cudaFuncAttributeMaxDynamicSharedMemorySize, D1_SMEM);

    zero_kernel<<<(N_P * 4 + 255) / 256, 256>>>();
    feat_kernel<<<128, 256, FEAT_SMEM>>>(x_src, Wfd, bfd);
    edge_kernel<<<4096, 256>>>(ei);
    node_kernel<<<6400, 256>>>(x_dst, Wl1, bl1, Wr1);
    conv_kernel<<<dim3(16, 64), 200, CONV_SMEM>>>(p_xp, Wc1, p_o1, L0, L1V);
    conv_kernel<<<dim3(16, 64), 200, CONV_SMEM>>>(p_o1, Wc2, p_o2, L1V, L2V);
    dense1_kernel<<<dim3(400, 16), 256, D1_SMEM>>>(p_o2, Wd1);
    dense2_kernel<<<NB, 128>>>(Wd2, out);
}

// round 7
// speedup vs baseline: 2.1662x; 1.0632x over previous
#include <cuda_runtime.h>
#include <cstdint>

// ---------------- problem constants ----------------
#define NB       16
#define N_F      524288
#define N_P      65536
#define EH       2097152
#define E_TOTAL  4194304
#define XP_N     6553600
#define L0       4096
#define L1V      4095
#define L2V      4094
#define KDIM     409400
#define O1       500
#define NCLS     107

// ---------------- packed fp32x2 helpers ----------------
__device__ __forceinline__ double pk2(float lo, float hi) {
    double d; asm("mov.b64 %0, {%1, %2};" : "=d"(d) : "f"(lo), "f"(hi)); return d;
}
__device__ __forceinline__ void upk2(double d, float& lo, float& hi) {
    asm("mov.b64 {%0, %1}, %2;" : "=f"(lo), "=f"(hi) : "d"(d));
}
__device__ __forceinline__ double ffma2(double a, double b, double c) {
    double d; asm("fma.rn.f32x2 %0, %1, %2, %3;" : "=d"(d) : "d"(a), "d"(b), "d"(c)); return d;
}
__device__ __forceinline__ double fadd2(double a, double b) {
    double d; asm("add.rn.f32x2 %0, %1, %2;" : "=d"(d) : "d"(a), "d"(b)); return d;
}

// ---------------- scratch ----------------
__device__ float4 g_xf4[N_F];
__device__ float g_agg[N_P * 4];
__device__ float g_xp[XP_N];
__device__ float g_out1[NB * 100 * L1V];
__device__ float g_out2[NB * 100 * L2V];
__device__ float g_y1[O1 * NB];

// ---------------- zero init ----------------
__global__ void zero_kernel() {
    int i = blockIdx.x * 256 + threadIdx.x;
    if (i < N_P * 4) g_agg[i] = 0.0f;
    if (i < O1 * NB) g_y1[i] = 0.0f;
}

// ---------------- feat: 8192x64 @ 64x192 -> g_xf4 ----------------
#define FEAT_SMEM ((64 * 65 + 192 * 65) * 4)
__global__ __launch_bounds__(256)
void feat_kernel(const float* __restrict__ xsrc,
                 const float* __restrict__ Wfd,
                 const float* __restrict__ bfd) {
    extern __shared__ float sm[];
    float* xs = sm;             // [64][65]
    float* ws = sm + 64 * 65;   // [192][65]
    int t = threadIdx.x;
    int i0 = blockIdx.x << 6;

    for (int idx = t; idx < 4096; idx += 256) {
        int i = idx >> 6, k = idx & 63;
        xs[i * 65 + k] = xsrc[(i0 + i) * 64 + k];
    }
    for (int idx = t; idx < 12288; idx += 256) {
        int j = idx >> 6, k = idx & 63;
        ws[j * 65 + k] = Wfd[idx];
    }
    __syncthreads();

    int tx = t & 15, ty = t >> 4;
    float acc[4][12];
#pragma unroll
    for (int ii = 0; ii < 4; ii++)
#pragma unroll
        for (int jj = 0; jj < 12; jj++) acc[ii][jj] = 0.0f;

    for (int k = 0; k < 64; k++) {
        float xv[4], wv[12];
#pragma unroll
        for (int ii = 0; ii < 4; ii++) xv[ii] = xs[(ty * 4 + ii) * 65 + k];
#pragma unroll
        for (int jj = 0; jj < 12; jj++) wv[jj] = ws[(tx * 12 + jj) * 65 + k];
#pragma unroll
        for (int ii = 0; ii < 4; ii++)
#pragma unroll
            for (int jj = 0; jj < 12; jj++)
                acc[ii][jj] = fmaf(xv[ii], wv[jj], acc[ii][jj]);
    }

    int j0 = tx * 12;
#pragma unroll
    for (int ii = 0; ii < 4; ii++) {
        int i = i0 + ty * 4 + ii;
#pragma unroll
        for (int rr = 0; rr < 4; rr++) {
            int r = i * 64 + tx * 4 + rr;
            g_xf4[r] = make_float4(
                acc[ii][rr * 3 + 0] + __ldg(bfd + j0 + rr * 3 + 0),
                acc[ii][rr * 3 + 1] + __ldg(bfd + j0 + rr * 3 + 1),
                acc[ii][rr * 3 + 2] + __ldg(bfd + j0 + rr * 3 + 2),
                0.0f);
        }
    }
}

// ---------------- edge aggregation ----------------
__global__ void edge_kernel(const int* __restrict__ ei) {
    int e2 = blockIdx.x * 256 + threadIdx.x;
    int4 s4 = *reinterpret_cast<const int4*>(ei + 4 * e2);
    int4 d4 = *reinterpret_cast<const int4*>(ei + E_TOTAL + 4 * e2);
    float4 v0 = g_xf4[s4.x];
    float4 v1 = g_xf4[s4.z];
    float* a0 = g_agg + 4 * d4.x;
    float* a1 = g_agg + 4 * d4.z;
    asm volatile("red.global.add.v4.f32 [%0], {%1, %2, %3, %4};"
                 :: "l"(a0), "f"(v0.x), "f"(v0.y), "f"(v0.z), "f"(1.0f) : "memory");
    asm volatile("red.global.add.v4.f32 [%0], {%1, %2, %3, %4};"
                 :: "l"(a1), "f"(v1.x), "f"(v1.y), "f"(v1.z), "f"(1.0f) : "memory");
}

// ---------------- node update ----------------
__global__ __launch_bounds__(256)
void node_kernel(const float* __restrict__ xdst,
                 const float* __restrict__ Wl1,
                 const float* __restrict__ bl1,
                 const float* __restrict__ Wr1) {
    __shared__ float swl[300], swr[300], sb[100];
    int t = threadIdx.x;
    for (int idx = t; idx < 300; idx += 256) { swl[idx] = Wl1[idx]; swr[idx] = Wr1[idx]; }
    if (t < 100) sb[t] = bl1[t];
    __syncthreads();

    int gid = blockIdx.x * 256 + t;
    int n = gid / 25;
    int c0 = (gid - n * 25) * 4;
    float4 a = *reinterpret_cast<const float4*>(&g_agg[n * 4]);
    float inv = __fdividef(1.0f, fmaxf(a.w, 1.0f));
    float m0 = a.x * inv, m1 = a.y * inv, m2 = a.z * inv;
    const float* xd = xdst + 3 * n;
    float d0 = xd[0], d1 = xd[1], d2 = xd[2];
    float r[4];
#pragma unroll
    for (int cc = 0; cc < 4; cc++) {
        int c = c0 + cc;
        float v = sb[c];
        v = fmaf(m0, swl[c * 3 + 0], v);
        v = fmaf(m1, swl[c * 3 + 1], v);
        v = fmaf(m2, swl[c * 3 + 2], v);
        v = fmaf(d0, swr[c * 3 + 0], v);
        v = fmaf(d1, swr[c * 3 + 1], v);
        v = fmaf(d2, swr[c * 3 + 2], v);
        r[cc] = fmaxf(v, 0.0f);
    }
    *reinterpret_cast<float4*>(&g_xp[n * 100 + c0]) =
        make_float4(r[0], r[1], r[2], r[3]);
}

// ---------------- conv (k=2, 100->100), packed f32x2 over k-pairs ----------------
#define CONV_SMEM ((100 * 202 + 100 * 68) * 4)
__global__ __launch_bounds__(200)
void conv_kernel(const float* __restrict__ in, const float* __restrict__ W,
                 float* __restrict__ out, int Lin, int Lout) {
    extern __shared__ float sm[];
    float* ws = sm;               // [o][202]
    float* xs = sm + 100 * 202;   // [i][68]
    int b  = blockIdx.x;
    int h0 = blockIdx.y << 6;
    int t  = threadIdx.x;

    for (int idx = t; idx < 20000; idx += 200) {
        int o = idx / 200;
        ws[o * 202 + (idx - o * 200)] = W[idx];
    }
    int nj = Lin - h0; if (nj > 65) nj = 65;
    const float* inb = in + b * 100 * Lin + h0;
    for (int idx = t; idx < 6800; idx += 200) {
        int i = idx / 68;
        int j = idx - i * 68;
        xs[idx] = (j < nj) ? inb[i * Lin + j] : 0.0f;
    }
    __syncthreads();

    int og = t >> 3, ht = t & 7;
    int o0 = og << 2, hh = ht << 3;
    double acc2[4][8];
#pragma unroll
    for (int oo = 0; oo < 4; oo++)
#pragma unroll
        for (int j = 0; j < 8; j++) acc2[oo][j] = 0.0;

    for (int i = 0; i < 100; i++) {
        const float* xr = xs + i * 68 + hh;
        float4 xA = *reinterpret_cast<const float4*>(xr);
        float4 xB = *reinterpret_cast<const float4*>(xr + 4);
        float x8 = xr[8];
        double xp[8];
        xp[0] = pk2(xA.x, xA.y); xp[1] = pk2(xA.y, xA.z);
        xp[2] = pk2(xA.z, xA.w); xp[3] = pk2(xA.w, xB.x);
        xp[4] = pk2(xB.x, xB.y); xp[5] = pk2(xB.y, xB.z);
        xp[6] = pk2(xB.z, xB.w); xp[7] = pk2(xB.w, x8);
#pragma unroll
        for (int oo = 0; oo < 4; oo++) {
            double wp = *reinterpret_cast<const double*>(&ws[(o0 + oo) * 202 + i * 2]);
#pragma unroll
            for (int j = 0; j < 8; j++)
                acc2[oo][j] = ffma2(wp, xp[j], acc2[oo][j]);
        }
    }

    float* outb = out + b * 100 * Lout;
#pragma unroll
    for (int oo = 0; oo < 4; oo++)
#pragma unroll
        for (int j = 0; j < 8; j++) {
            int h = h0 + hh + j;
            if (h < Lout) {
                float lo, hi; upk2(acc2[oo][j], lo, hi);
                outb[(o0 + oo) * Lout + h] = fmaxf(lo + hi, 0.0f);
            }
        }
}

// ---------------- dense1 v4: lean inner loop (no pk2/copies), conflict-free stage -
// grid (400 k-chunks, 16 o-tiles). block 256 = 8 warps x 4 o. lane = k (stride 32).
// xs: [k][b] rows of 20 floats = 10 doubles; b-pairs are native double2 loads.
#define D1_SMEM (1024 * 20 * 4)
__global__ __launch_bounds__(256, 2)
void dense1_kernel(const float* __restrict__ x2, const float* __restrict__ W) {
    extern __shared__ float xs[];   // [1024][20]
    int t = threadIdx.x;
    int k0 = blockIdx.x << 10;
    int KN = KDIM - k0; if (KN > 1024) KN = 1024;

    // staging: b = idx & 15 -> consecutive threads hit consecutive banks (no STS conflicts)
    for (int idx = t; idx < 4096; idx += 256) {
        int b  = idx & 15;
        int kk = (idx >> 4) << 2;
        float4 v = make_float4(0.f, 0.f, 0.f, 0.f);
        if (kk < KN)
            v = *reinterpret_cast<const float4*>(x2 + (size_t)b * KDIM + k0 + kk);
        xs[(kk + 0) * 20 + b] = v.x;
        xs[(kk + 1) * 20 + b] = v.y;
        xs[(kk + 2) * 20 + b] = v.z;
        xs[(kk + 3) * 20 + b] = v.w;
    }
    __syncthreads();

    int wid = t >> 5, lane = t & 31;
    int o0 = (blockIdx.y << 5) + (wid << 2);
    if (o0 >= O1) return;

    double acc2[4][8];   // [o][b-pair], packed fp32x2
#pragma unroll
    for (int o = 0; o < 4; o++)
#pragma unroll
        for (int bp = 0; bp < 8; bp++) acc2[o][bp] = 0.0;

    const float* wbase = W + (size_t)o0 * KDIM + k0;

    // prologue: prefetch iterations 0..3
    float wbuf[4][4];    // [slot][o]
#pragma unroll
    for (int p = 0; p < 4; p++) {
        int k = lane + (p << 5);
#pragma unroll
        for (int o = 0; o < 4; o++)
            wbuf[p][o] = (k < KN) ? __ldg(wbase + (size_t)o * KDIM + k) : 0.0f;
    }

#pragma unroll 4
    for (int it = 0; it < 32; it++) {
        int slot = it & 3;
        int k = lane + (it << 5);

        // duplicate w into packed halves (consumes wbuf[slot], freeing it)
        double wd[4];
#pragma unroll
        for (int o = 0; o < 4; o++) wd[o] = pk2(wbuf[slot][o], wbuf[slot][o]);

        // refill slot for it+4 immediately (long dependency distance)
        int kn = k + 128;
#pragma unroll
        for (int o = 0; o < 4; o++)
            wbuf[slot][o] = (kn < KN) ? __ldg(wbase + (size_t)o * KDIM + kn) : 0.0f;

        // x pairs: direct double2 loads (layout is already pair-packed)
        const double2* xrow = reinterpret_cast<const double2*>(&xs[k * 20]);
        double2 x01 = xrow[0], x23 = xrow[1], x45 = xrow[2], x67 = xrow[3];
        double xp[8] = {x01.x, x01.y, x23.x, x23.y, x45.x, x45.y, x67.x, x67.y};

#pragma unroll
        for (int o = 0; o < 4; o++)
#pragma unroll
            for (int bp = 0; bp < 8; bp++)
                acc2[o][bp] = ffma2(wd[o], xp[bp], acc2[o][bp]);
    }

    // halving butterfly on 32 packed pairs with packed adds
    double s2[32];
#pragma unroll
    for (int a = 0; a < 32; a++) s2[a] = acc2[a >> 3][a & 7];
    int n = 32;
#pragma unroll
    for (int d = 16; d >= 1; d >>= 1) {
        n >>= 1;
        bool hiSel = (lane & d) != 0;
#pragma unroll
        for (int i = 0; i < 16; i++) {
            if (i >= n) break;
            double send = hiSel ? s2[i] : s2[i + n];
            double recv = __shfl_xor_sync(0xffffffffu, send, d);
            double keep = hiSel ? s2[i + n] : s2[i];
            s2[i] = fadd2(keep, recv);
        }
    }
    float lo, hi; upk2(s2[0], lo, hi);
    float* addr = &g_y1[(o0 + (lane >> 3)) * 16 + 2 * (lane & 7)];
    asm volatile("red.global.add.v2.f32 [%0], {%1, %2};"
                 :: "l"(addr), "f"(lo), "f"(hi) : "memory");
}

// ---------------- dense2 + softmax ----------------
__global__ void dense2_kernel(const float* __restrict__ Wd2, float* __restrict__ out) {
    __shared__ float ys[O1];
    __shared__ float red[128];
    int b = blockIdx.x, t = threadIdx.x;
    for (int o = t; o < O1; o += 128) ys[o] = fmaxf(g_y1[o * 16 + b], 0.0f);
    __syncthreads();

    float logit = -1e30f;
    if (t < NCLS) {
        float s = 0.0f;
        const float* wr = Wd2 + t * O1;
        for (int o = 0; o < O1; o++) s = fmaf(ys[o], __ldg(wr + o), s);
        logit = s;
    }
    red[t] = logit;
    __syncthreads();
    for (int s = 64; s > 0; s >>= 1) {
        if (t < s) red[t] = fmaxf(red[t], red[t + s]);
        __syncthreads();
    }
    float mx = red[0];
    __syncthreads();
    float e = (t < NCLS) ? expf(logit - mx) : 0.0f;
    red[t] = e;
    __syncthreads();
    for (int s = 64; s > 0; s >>= 1) {
        if (t < s) red[t] += red[t + s];
        __syncthreads();
    }
    float sum = red[0];
    if (t < NCLS) out[b * NCLS + t] = e / sum;
}

// ---------------- launch ----------------
extern "C" void kernel_launch(void* const* d_in, const int* in_sizes, int n_in,
                              void* d_out, int out_size) {
    const float* x_src = (const float*)d_in[0];
    const float* x_dst = (const float*)d_in[1];
    const int*   ei    = (const int*)  d_in[2];
    const float* Wfd   = (const float*)d_in[3];
    const float* bfd   = (const float*)d_in[4];
    const float* Wl1   = (const float*)d_in[5];
    const float* bl1   = (const float*)d_in[6];
    const float* Wr1   = (const float*)d_in[7];
    const float* Wc1   = (const float*)d_in[11];
    const float* Wc2   = (const float*)d_in[12];
    const float* Wd1   = (const float*)d_in[13];
    const float* Wd2   = (const float*)d_in[14];
    float* out = (float*)d_out;

    float *p_xp, *p_o1, *p_o2;
    cudaGetSymbolAddress((void**)&p_xp, g_xp);
    cudaGetSymbolAddress((void**)&p_o1, g_out1);
    cudaGetSymbolAddress((void**)&p_o2, g_out2);

    cudaFuncSetAttribute(feat_kernel,   cudaFuncAttributeMaxDynamicSharedMemorySize, FEAT_SMEM);
    cudaFuncSetAttribute(conv_kernel,   cudaFuncAttributeMaxDynamicSharedMemorySize, CONV_SMEM);
    cudaFuncSetAttribute(dense1_kernel, cudaFuncAttributeMaxDynamicSharedMemorySize, D1_SMEM);
    // ensure smem carveout allows 2 resident blocks (2 x 80KB)
    cudaFuncSetAttribute(dense1_kernel, cudaFuncAttributePreferredSharedMemoryCarveout, 100);

    zero_kernel<<<(N_P * 4 + 255) / 256, 256>>>();
    feat_kernel<<<128, 256, FEAT_SMEM>>>(x_src, Wfd, bfd);
    edge_kernel<<<4096, 256>>>(ei);
    node_kernel<<<6400, 256>>>(x_dst, Wl1, bl1, Wr1);
    conv_kernel<<<dim3(16, 64), 200, CONV_SMEM>>>(p_xp, Wc1, p_o1, L0, L1V);
    conv_kernel<<<dim3(16, 64), 200, CONV_SMEM>>>(p_o1, Wc2, p_o2, L1V, L2V);
    dense1_kernel<<<dim3(400, 16), 256, D1_SMEM>>>(p_o2, Wd1);
    dense2_kernel<<<NB, 128>>>(Wd2, out);
}